// round 11
// baseline (speedup 1.0000x reference)
#include <cuda_runtime.h>

// Problem constants (shapes fixed by the dataset): B=8192, S=4096.
#define MAX_B   8192
#define THREADS 256
#define WARPS_PER_CTA 8
#define PF_DIST 256   // prefetch distance in float4s (2 unrolled bodies ahead)

#define LOG2E 1.4426950408889634f
#define LN2   0.6931471805599453f

__device__ float g_partial[MAX_B];
__device__ unsigned int g_done = 0;

__device__ __forceinline__ float ex2f(float x) {
    float y; asm("ex2.approx.ftz.f32 %0, %1;" : "=f"(y) : "f"(x)); return y;
}
__device__ __forceinline__ float lg2f(float x) {
    float y; asm("lg2.approx.ftz.f32 %0, %1;" : "=f"(y) : "f"(x)); return y;
}
__device__ __forceinline__ float rcpf(float x) {
    float y; asm("rcp.approx.ftz.f32 %0, %1;" : "=f"(y) : "f"(x)); return y;
}
__device__ __forceinline__ void prefetch_l2(const void* p) {
    asm volatile("prefetch.global.L2 [%0];" :: "l"(p));
}

// Per-element focal term in log2 domain (missing the final *ln2 scale):
//   t   = d * log2e,  ep = 2^t,  u = 1 + ep
//   om  = sigmoid(d)      = ep / u
//   sp2 = softplus(d)/ln2 = lg2(u)
//   fl2 = om^2 * sp2      (true fl = fl2 * ln2)
// 3 MUFU total (ex2, rcp, lg2).
__device__ __forceinline__ float focal2(float t) {
    const float ep  = ex2f(t);
    const float u   = 1.0f + ep;
    const float om  = ep * rcpf(u);
    const float sp2 = lg2f(u);
    return om * om * sp2;
}

// One WARP per row; grid = B/8 CTAs of 256 threads -> 8192 warps = 8192 rows,
// a single resident wave. Each lane streams 32 float4/int4 pairs with an L2
// prefetch running PF_DIST float4s ahead (register-free latency hiding).
// Warp-shuffle reduction only in the hot path.
// mask values are exactly {0,1}; head/tail exclusion via a per-row correction
// on lane 0 instead of per-element compares.
__global__ void __launch_bounds__(THREADS, 8)
focal_fused_kernel(const float* __restrict__ scores,
                   const int* __restrict__ head,
                   const int* __restrict__ tail,
                   const int* __restrict__ mask,
                   float* __restrict__ out,
                   int S, int B)
{
    const int tid = threadIdx.x;
    const int wid = tid >> 5;
    const int lid = tid & 31;
    const int row = blockIdx.x * WARPS_PER_CTA + wid;

    const float* __restrict__ srow = scores + (size_t)row * S;
    const int*   __restrict__ mrow = mask   + (size_t)row * S;

    const int hp = head[row];
    const int tp = tail[row];
    const float pos  = __ldg(srow + tp);
    const float pos2 = pos * LOG2E;

    float sum2 = 0.0f;
    int   cnt  = 0;

    // Lane 0 pre-subtracts the head/tail contributions that the mask-only
    // loop below will (wrongly) include.
    if (lid == 0) {
        const int m_tp = __ldg(mrow + tp);
        if (m_tp == 1) {
            // d = 0 exactly: om = 0.5, sp2 = 1 -> fl2 = 0.25
            sum2 -= 0.25f;
            cnt  -= 1;
        }
        if (hp != tp) {
            const int m_hp = __ldg(mrow + hp);
            if (m_hp == 1) {
                const float s = __ldg(srow + hp);
                const float t = fmaf(s, LOG2E, -pos2);
                sum2 -= focal2(t);
                cnt  -= 1;
            }
        }
    }

    const int n4 = S >> 2;   // float4s per row (1024); 32 per lane

    #pragma unroll 4
    for (int i = lid; i < n4; i += 32) {
        // Register-free latency hiding: pull future lines DRAM -> L2.
        if (i + PF_DIST < n4) {
            prefetch_l2(reinterpret_cast<const float4*>(srow) + i + PF_DIST);
            prefetch_l2(reinterpret_cast<const int4*>(mrow)   + i + PF_DIST);
        }

        const float4 sv = reinterpret_cast<const float4*>(srow)[i];
        const int4   mv = reinterpret_cast<const int4*>(mrow)[i];

        const float sarr[4] = { sv.x, sv.y, sv.z, sv.w };
        const int   marr[4] = { mv.x, mv.y, mv.z, mv.w };
        #pragma unroll
        for (int j = 0; j < 4; ++j) {
            const float t   = fmaf(sarr[j], LOG2E, -pos2);
            const float fl2 = focal2(t);
            // mask in {0,1}: build 0.0f/1.0f weight with one IMAD (no I2F)
            const float mf  = __int_as_float(marr[j] * 0x3f800000);
            sum2 = fmaf(fl2, mf, sum2);
            cnt += marr[j];
        }
    }

    // Warp-only deterministic reduction (fixed shuffle order).
    #pragma unroll
    for (int o = 16; o > 0; o >>= 1) {
        sum2 += __shfl_down_sync(0xffffffffu, sum2, o);
        cnt  += __shfl_down_sync(0xffffffffu, cnt, o);
    }
    if (lid == 0)
        g_partial[row] = (cnt > 0) ? sum2 / (float)cnt : 0.0f;

    // Completion protocol: last CTA reduces all B partials in fixed order.
    __shared__ bool is_last;
    __syncthreads();
    if (tid == 0) {
        __threadfence();
        const unsigned int old = atomicAdd(&g_done, 1u);
        is_last = (old == (unsigned int)(gridDim.x - 1));
    }
    __syncthreads();

    if (is_last) {
        float fsum = 0.0f;
        const int nb4 = B >> 2;
        for (int i = tid; i < nb4; i += THREADS) {
            const float4 v = reinterpret_cast<const float4*>(g_partial)[i];
            fsum += (v.x + v.y) + (v.z + v.w);
        }
        #pragma unroll
        for (int o = 16; o > 0; o >>= 1)
            fsum += __shfl_down_sync(0xffffffffu, fsum, o);
        __shared__ float fs[8];
        if (lid == 0) fs[wid] = fsum;
        __syncthreads();
        if (wid == 0) {
            fsum = (lid < 8) ? fs[lid] : 0.0f;
            #pragma unroll
            for (int o = 4; o > 0; o >>= 1)
                fsum += __shfl_down_sync(0xffffffffu, fsum, o);
            if (lid == 0) {
                out[0] = fsum * (LN2 / (float)B);   // fold ln2 scale here
                g_done = 0;                          // reset for graph replay
            }
        }
    }
}

extern "C" void kernel_launch(void* const* d_in, const int* in_sizes, int n_in,
                              void* d_out, int out_size)
{
    // metadata order: scores [B,S] f32, head [B] i32, tail [B] i32, mask [B,S] i32
    const float* scores = (const float*)d_in[0];
    const int*   head   = (const int*)d_in[1];
    const int*   tail   = (const int*)d_in[2];
    const int*   mask   = (const int*)d_in[3];
    float* out = (float*)d_out;

    const int B = in_sizes[1];
    const int S = in_sizes[0] / B;

    const int grid = B / WARPS_PER_CTA;   // 1024 CTAs, one warp per row
    focal_fused_kernel<<<grid, THREADS>>>(scores, head, tail, mask, out, S, B);
}

// round 12
// speedup vs baseline: 1.2822x; 1.2822x over previous
#include <cuda_runtime.h>

// Problem constants (shapes fixed by the dataset): B=8192, S=4096.
#define MAX_B   8192
#define THREADS 256
#define WARPS_PER_CTA 8
#define PF_DIST 32    // prefetch ONE iteration ahead (512B/warp/stream window)

#define LOG2E 1.4426950408889634f
#define LN2   0.6931471805599453f

__device__ float g_partial[MAX_B];
__device__ unsigned int g_done = 0;

__device__ __forceinline__ float ex2f(float x) {
    float y; asm("ex2.approx.ftz.f32 %0, %1;" : "=f"(y) : "f"(x)); return y;
}
__device__ __forceinline__ float lg2f(float x) {
    float y; asm("lg2.approx.ftz.f32 %0, %1;" : "=f"(y) : "f"(x)); return y;
}
__device__ __forceinline__ float rcpf(float x) {
    float y; asm("rcp.approx.ftz.f32 %0, %1;" : "=f"(y) : "f"(x)); return y;
}
__device__ __forceinline__ void prefetch_l2(const void* p) {
    asm volatile("prefetch.global.L2 [%0];" :: "l"(p));
}

// Per-element focal term in log2 domain (missing the final *ln2 scale):
//   t   = d * log2e,  ep = 2^t,  u = 1 + ep
//   om  = sigmoid(d)      = ep / u
//   sp2 = softplus(d)/ln2 = lg2(u)
//   fl2 = om^2 * sp2      (true fl = fl2 * ln2)
// 3 MUFU total (ex2, rcp, lg2).
__device__ __forceinline__ float focal2(float t) {
    const float ep  = ex2f(t);
    const float u   = 1.0f + ep;
    const float om  = ep * rcpf(u);
    const float sp2 = lg2f(u);
    return om * om * sp2;
}

// One WARP per row; grid = B/8 CTAs of 256 threads -> 8192 warps = 8192 rows,
// a single resident wave. Each lane streams 32 float4/int4 pairs with an L2
// prefetch running exactly one iteration ahead: far enough to cover DRAM
// latency (~577cyc << ~2900cyc/iter), small enough (~8MB chip-wide window)
// not to thrash L2 (the R11 failure mode at PF_DIST=256).
// Warp-shuffle reduction only in the hot path.
// mask values are exactly {0,1}; head/tail exclusion via a per-row correction
// on lane 0 instead of per-element compares.
__global__ void __launch_bounds__(THREADS, 8)
focal_fused_kernel(const float* __restrict__ scores,
                   const int* __restrict__ head,
                   const int* __restrict__ tail,
                   const int* __restrict__ mask,
                   float* __restrict__ out,
                   int S, int B)
{
    const int tid = threadIdx.x;
    const int wid = tid >> 5;
    const int lid = tid & 31;
    const int row = blockIdx.x * WARPS_PER_CTA + wid;

    const float* __restrict__ srow = scores + (size_t)row * S;
    const int*   __restrict__ mrow = mask   + (size_t)row * S;

    const int hp = head[row];
    const int tp = tail[row];
    const float pos  = __ldg(srow + tp);
    const float pos2 = pos * LOG2E;

    float sum2 = 0.0f;
    int   cnt  = 0;

    // Lane 0 pre-subtracts the head/tail contributions that the mask-only
    // loop below will (wrongly) include.
    if (lid == 0) {
        const int m_tp = __ldg(mrow + tp);
        if (m_tp == 1) {
            // d = 0 exactly: om = 0.5, sp2 = 1 -> fl2 = 0.25
            sum2 -= 0.25f;
            cnt  -= 1;
        }
        if (hp != tp) {
            const int m_hp = __ldg(mrow + hp);
            if (m_hp == 1) {
                const float s = __ldg(srow + hp);
                const float t = fmaf(s, LOG2E, -pos2);
                sum2 -= focal2(t);
                cnt  -= 1;
            }
        }
    }

    const int n4 = S >> 2;   // float4s per row (1024); 32 per lane

    #pragma unroll 4
    for (int i = lid; i < n4; i += 32) {
        // Pull next iteration's lines DRAM -> L2 (register-free MLP).
        if (i + PF_DIST < n4) {
            prefetch_l2(reinterpret_cast<const float4*>(srow) + i + PF_DIST);
            prefetch_l2(reinterpret_cast<const int4*>(mrow)   + i + PF_DIST);
        }

        const float4 sv = reinterpret_cast<const float4*>(srow)[i];
        const int4   mv = reinterpret_cast<const int4*>(mrow)[i];

        const float sarr[4] = { sv.x, sv.y, sv.z, sv.w };
        const int   marr[4] = { mv.x, mv.y, mv.z, mv.w };
        #pragma unroll
        for (int j = 0; j < 4; ++j) {
            const float t   = fmaf(sarr[j], LOG2E, -pos2);
            const float fl2 = focal2(t);
            // mask in {0,1}: build 0.0f/1.0f weight with one IMAD (no I2F)
            const float mf  = __int_as_float(marr[j] * 0x3f800000);
            sum2 = fmaf(fl2, mf, sum2);
            cnt += marr[j];
        }
    }

    // Warp-only deterministic reduction (fixed shuffle order).
    #pragma unroll
    for (int o = 16; o > 0; o >>= 1) {
        sum2 += __shfl_down_sync(0xffffffffu, sum2, o);
        cnt  += __shfl_down_sync(0xffffffffu, cnt, o);
    }
    if (lid == 0)
        g_partial[row] = (cnt > 0) ? sum2 / (float)cnt : 0.0f;

    // Completion protocol: last CTA reduces all B partials in fixed order.
    __shared__ bool is_last;
    __syncthreads();
    if (tid == 0) {
        __threadfence();
        const unsigned int old = atomicAdd(&g_done, 1u);
        is_last = (old == (unsigned int)(gridDim.x - 1));
    }
    __syncthreads();

    if (is_last) {
        float fsum = 0.0f;
        const int nb4 = B >> 2;
        for (int i = tid; i < nb4; i += THREADS) {
            const float4 v = reinterpret_cast<const float4*>(g_partial)[i];
            fsum += (v.x + v.y) + (v.z + v.w);
        }
        #pragma unroll
        for (int o = 16; o > 0; o >>= 1)
            fsum += __shfl_down_sync(0xffffffffu, fsum, o);
        __shared__ float fs[8];
        if (lid == 0) fs[wid] = fsum;
        __syncthreads();
        if (wid == 0) {
            fsum = (lid < 8) ? fs[lid] : 0.0f;
            #pragma unroll
            for (int o = 4; o > 0; o >>= 1)
                fsum += __shfl_down_sync(0xffffffffu, fsum, o);
            if (lid == 0) {
                out[0] = fsum * (LN2 / (float)B);   // fold ln2 scale here
                g_done = 0;                          // reset for graph replay
            }
        }
    }
}

extern "C" void kernel_launch(void* const* d_in, const int* in_sizes, int n_in,
                              void* d_out, int out_size)
{
    // metadata order: scores [B,S] f32, head [B] i32, tail [B] i32, mask [B,S] i32
    const float* scores = (const float*)d_in[0];
    const int*   head   = (const int*)d_in[1];
    const int*   tail   = (const int*)d_in[2];
    const int*   mask   = (const int*)d_in[3];
    float* out = (float*)d_out;

    const int B = in_sizes[1];
    const int S = in_sizes[0] / B;

    const int grid = B / WARPS_PER_CTA;   // 1024 CTAs, one warp per row
    focal_fused_kernel<<<grid, THREADS>>>(scores, head, tail, mask, out, S, B);
}

// round 13
// speedup vs baseline: 1.3293x; 1.0367x over previous
#include <cuda_runtime.h>
#include <cstdint>

// Problem constants (shapes fixed by the dataset): B=8192, S=4096.
#define MAX_B   8192
#define THREADS 256
#define WARPS_PER_CTA 8

#define LOG2E 1.4426950408889634f
#define LN2   0.6931471805599453f

__device__ float g_partial[MAX_B];
__device__ unsigned int g_done = 0;

__device__ __forceinline__ float ex2f(float x) {
    float y; asm("ex2.approx.ftz.f32 %0, %1;" : "=f"(y) : "f"(x)); return y;
}
__device__ __forceinline__ float lg2f(float x) {
    float y; asm("lg2.approx.ftz.f32 %0, %1;" : "=f"(y) : "f"(x)); return y;
}
__device__ __forceinline__ float rcpf(float x) {
    float y; asm("rcp.approx.ftz.f32 %0, %1;" : "=f"(y) : "f"(x)); return y;
}
__device__ __forceinline__ void cp_async16(uint32_t saddr, const void* gptr) {
    asm volatile("cp.async.cg.shared.global [%0], [%1], 16;"
                 :: "r"(saddr), "l"(gptr));
}
#define CP_COMMIT() asm volatile("cp.async.commit_group;" ::: "memory")
#define CP_WAIT(n)  asm volatile("cp.async.wait_group %0;" :: "n"(n) : "memory")

// Per-element focal term in log2 domain (missing the final *ln2 scale):
//   t   = d * log2e,  ep = 2^t,  u = 1 + ep
//   om  = sigmoid(d)      = ep / u
//   sp2 = softplus(d)/ln2 = lg2(u)
//   fl2 = om^2 * sp2      (true fl = fl2 * ln2)
// 3 MUFU total (ex2, rcp, lg2).
__device__ __forceinline__ float focal2(float t) {
    const float ep  = ex2f(t);
    const float u   = 1.0f + ep;
    const float om  = ep * rcpf(u);
    const float sp2 = lg2f(u);
    return om * om * sp2;
}

// One WARP per row; grid = B/8 CTAs -> 8192 warps = 8192 rows, single wave.
// Streaming via cp.async.cg double-buffer: each lane stages its own 16B of
// scores + 16B of mask per stage into a private smem slot, then reads back
// only its own bytes -> per-thread wait_group is sufficient, no __syncwarp.
// This decouples loads-in-flight from the register file (~54KB/SM in flight
// vs ~25KB needed to cover DRAM latency), which LDG at 32 regs cannot do.
// mask values are exactly {0,1}; head/tail exclusion via a per-row correction
// on lane 0 instead of per-element compares.
__global__ void __launch_bounds__(THREADS, 8)
focal_fused_kernel(const float* __restrict__ scores,
                   const int* __restrict__ head,
                   const int* __restrict__ tail,
                   const int* __restrict__ mask,
                   float* __restrict__ out,
                   int S, int B)
{
    __shared__ float4 sbuf[WARPS_PER_CTA][2][32];
    __shared__ int4   mbuf[WARPS_PER_CTA][2][32];

    const int tid = threadIdx.x;
    const int wid = tid >> 5;
    const int lid = tid & 31;
    const int row = blockIdx.x * WARPS_PER_CTA + wid;

    const float* __restrict__ srow = scores + (size_t)row * S;
    const int*   __restrict__ mrow = mask   + (size_t)row * S;
    const float4* __restrict__ srow4 = reinterpret_cast<const float4*>(srow);
    const int4*   __restrict__ mrow4 = reinterpret_cast<const int4*>(mrow);

    const uint32_t sb0 = (uint32_t)__cvta_generic_to_shared(&sbuf[wid][0][lid]);
    const uint32_t sb1 = (uint32_t)__cvta_generic_to_shared(&sbuf[wid][1][lid]);
    const uint32_t mb0 = (uint32_t)__cvta_generic_to_shared(&mbuf[wid][0][lid]);
    const uint32_t mb1 = (uint32_t)__cvta_generic_to_shared(&mbuf[wid][1][lid]);

    const int hp = head[row];
    const int tp = tail[row];
    const float pos  = __ldg(srow + tp);
    const float pos2 = pos * LOG2E;

    float sum2 = 0.0f;
    int   cnt  = 0;

    // Lane 0 pre-subtracts the head/tail contributions that the mask-only
    // loop below will (wrongly) include.
    if (lid == 0) {
        const int m_tp = __ldg(mrow + tp);
        if (m_tp == 1) {
            // d = 0 exactly: om = 0.5, sp2 = 1 -> fl2 = 0.25
            sum2 -= 0.25f;
            cnt  -= 1;
        }
        if (hp != tp) {
            const int m_hp = __ldg(mrow + hp);
            if (m_hp == 1) {
                const float s = __ldg(srow + hp);
                const float t = fmaf(s, LOG2E, -pos2);
                sum2 -= focal2(t);
                cnt  -= 1;
            }
        }
    }

    const int n4      = S >> 2;      // float4s per row (1024)
    const int nstages = n4 >> 5;     // 32 stages of (32 float4 + 32 int4)

    // Prologue: stage 0 in flight.
    cp_async16(sb0, srow4 + lid);
    cp_async16(mb0, mrow4 + lid);
    CP_COMMIT();

    for (int s = 0; s < nstages - 1; ++s) {
        const int cur = s & 1, nxt = cur ^ 1;
        // Issue stage s+1 (one group), then wait until only it is pending
        // -> stage s's bytes (this lane's own copies) have landed in smem.
        const int base = (s + 1) << 5;
        cp_async16(nxt ? sb1 : sb0, srow4 + base + lid);
        cp_async16(nxt ? mb1 : mb0, mrow4 + base + lid);
        CP_COMMIT();
        CP_WAIT(1);

        const float4 sv = sbuf[wid][cur][lid];
        const int4   mv = mbuf[wid][cur][lid];
        const float sarr[4] = { sv.x, sv.y, sv.z, sv.w };
        const int   marr[4] = { mv.x, mv.y, mv.z, mv.w };
        #pragma unroll
        for (int j = 0; j < 4; ++j) {
            const float t   = fmaf(sarr[j], LOG2E, -pos2);
            const float fl2 = focal2(t);
            // mask in {0,1}: build 0.0f/1.0f weight with one IMAD (no I2F)
            const float mf  = __int_as_float(marr[j] * 0x3f800000);
            sum2 = fmaf(fl2, mf, sum2);
            cnt += marr[j];
        }
    }

    // Epilogue: last stage.
    CP_WAIT(0);
    {
        const int cur = (nstages - 1) & 1;
        const float4 sv = sbuf[wid][cur][lid];
        const int4   mv = mbuf[wid][cur][lid];
        const float sarr[4] = { sv.x, sv.y, sv.z, sv.w };
        const int   marr[4] = { mv.x, mv.y, mv.z, mv.w };
        #pragma unroll
        for (int j = 0; j < 4; ++j) {
            const float t   = fmaf(sarr[j], LOG2E, -pos2);
            const float fl2 = focal2(t);
            const float mf  = __int_as_float(marr[j] * 0x3f800000);
            sum2 = fmaf(fl2, mf, sum2);
            cnt += marr[j];
        }
    }

    // Warp-only deterministic reduction (fixed shuffle order).
    #pragma unroll
    for (int o = 16; o > 0; o >>= 1) {
        sum2 += __shfl_down_sync(0xffffffffu, sum2, o);
        cnt  += __shfl_down_sync(0xffffffffu, cnt, o);
    }
    if (lid == 0)
        g_partial[row] = (cnt > 0) ? sum2 / (float)cnt : 0.0f;

    // Completion protocol: last CTA reduces all B partials in fixed order.
    __shared__ bool is_last;
    __syncthreads();
    if (tid == 0) {
        __threadfence();
        const unsigned int old = atomicAdd(&g_done, 1u);
        is_last = (old == (unsigned int)(gridDim.x - 1));
    }
    __syncthreads();

    if (is_last) {
        float fsum = 0.0f;
        const int nb4 = B >> 2;
        for (int i = tid; i < nb4; i += THREADS) {
            const float4 v = reinterpret_cast<const float4*>(g_partial)[i];
            fsum += (v.x + v.y) + (v.z + v.w);
        }
        #pragma unroll
        for (int o = 16; o > 0; o >>= 1)
            fsum += __shfl_down_sync(0xffffffffu, fsum, o);
        __shared__ float fs[8];
        if (lid == 0) fs[wid] = fsum;
        __syncthreads();
        if (wid == 0) {
            fsum = (lid < 8) ? fs[lid] : 0.0f;
            #pragma unroll
            for (int o = 4; o > 0; o >>= 1)
                fsum += __shfl_down_sync(0xffffffffu, fsum, o);
            if (lid == 0) {
                out[0] = fsum * (LN2 / (float)B);   // fold ln2 scale here
                g_done = 0;                          // reset for graph replay
            }
        }
    }
}

extern "C" void kernel_launch(void* const* d_in, const int* in_sizes, int n_in,
                              void* d_out, int out_size)
{
    // metadata order: scores [B,S] f32, head [B] i32, tail [B] i32, mask [B,S] i32
    const float* scores = (const float*)d_in[0];
    const int*   head   = (const int*)d_in[1];
    const int*   tail   = (const int*)d_in[2];
    const int*   mask   = (const int*)d_in[3];
    float* out = (float*)d_out;

    const int B = in_sizes[1];
    const int S = in_sizes[0] / B;

    const int grid = B / WARPS_PER_CTA;   // 1024 CTAs, one warp per row
    focal_fused_kernel<<<grid, THREADS>>>(scores, head, tail, mask, out, S, B);
}